// round 1
// baseline (speedup 1.0000x reference)
#include <cuda_runtime.h>

#define NN 10000
#define DD 128
#define EE 640000

// ---------------- device scratch (no allocations allowed) ----------------
__device__ int   g_deg[NN];
__device__ int   g_rowptr[NN + 1];
__device__ int   g_cursor[NN];
__device__ int   g_srcs[EE];
__device__ float g_agg[NN * DD];
__device__ int   g_is64;

// ---------------- dtype detection: int64 vs int32 edge_index -------------
// int64 values < 10000 => every odd int32 word is 0 (little endian).
__global__ void k_detect(const int* __restrict__ ei) {
    if (blockIdx.x == 0 && threadIdx.x == 0) {
        int all0 = 1;
        for (int i = 0; i < 512; i++) {
            if (ei[2 * i + 1] != 0) { all0 = 0; break; }
        }
        g_is64 = all0;
    }
}

__global__ void k_zero() {
    int i = blockIdx.x * 256 + threadIdx.x;
    if (i < NN) g_deg[i] = 0;
}

__device__ __forceinline__ int load_idx(const void* ei, long long pos) {
    if (g_is64) return (int)((const long long*)ei)[pos];
    return ((const int*)ei)[pos];
}

__global__ void k_hist(const void* __restrict__ ei, int E) {
    int e = blockIdx.x * 256 + threadIdx.x;
    if (e < E) {
        int dst = load_idx(ei, (long long)E + e);
        atomicAdd(&g_deg[dst], 1);
    }
}

// single-block exclusive scan over g_deg -> g_rowptr, g_cursor
__global__ void k_scan() {
    const int T = 1024;
    const int C = (NN + T - 1) / T;   // 10
    __shared__ int s[T];
    int t = threadIdx.x;
    int base = t * C;
    int sum = 0;
#pragma unroll
    for (int i = 0; i < C; i++) {
        int idx = base + i;
        if (idx < NN) sum += g_deg[idx];
    }
    s[t] = sum;
    __syncthreads();
    for (int off = 1; off < T; off <<= 1) {
        int v = (t >= off) ? s[t - off] : 0;
        __syncthreads();
        s[t] += v;
        __syncthreads();
    }
    int run = s[t] - sum;   // exclusive prefix for this chunk
#pragma unroll
    for (int i = 0; i < C; i++) {
        int idx = base + i;
        if (idx < NN) {
            g_rowptr[idx] = run;
            g_cursor[idx] = run;
            run += g_deg[idx];
        }
    }
    if (t == T - 1) g_rowptr[NN] = s[T - 1];
}

__global__ void k_scatter(const void* __restrict__ ei, int E) {
    int e = blockIdx.x * 256 + threadIdx.x;
    if (e < E) {
        int dst = load_idx(ei, (long long)E + e);
        int src = load_idx(ei, e);
        int pos = atomicAdd(&g_cursor[dst], 1);
        g_srcs[pos] = src;
    }
}

// one warp per node; lane owns 4 feature columns (float4); 4-deep accumulators
__global__ void k_agg(const float* __restrict__ x) {
    int gw   = (blockIdx.x * blockDim.x + threadIdx.x) >> 5;
    int lane = threadIdx.x & 31;
    if (gw >= NN) return;
    int s = g_rowptr[gw], e = g_rowptr[gw + 1];
    float4 a0 = {0,0,0,0}, a1 = {0,0,0,0}, a2 = {0,0,0,0}, a3 = {0,0,0,0};
    const float* xcol = x + lane * 4;
    for (int base = s; base < e; base += 32) {
        int m = e - base; if (m > 32) m = 32;
        int sid = 0;
        if (lane < m) sid = g_srcs[base + lane];
        int i = 0;
        for (; i + 4 <= m; i += 4) {
            int s0 = __shfl_sync(0xffffffffu, sid, i);
            int s1 = __shfl_sync(0xffffffffu, sid, i + 1);
            int s2 = __shfl_sync(0xffffffffu, sid, i + 2);
            int s3 = __shfl_sync(0xffffffffu, sid, i + 3);
            float4 v0 = *(const float4*)(xcol + (size_t)s0 * DD);
            float4 v1 = *(const float4*)(xcol + (size_t)s1 * DD);
            float4 v2 = *(const float4*)(xcol + (size_t)s2 * DD);
            float4 v3 = *(const float4*)(xcol + (size_t)s3 * DD);
            a0.x += v0.x; a0.y += v0.y; a0.z += v0.z; a0.w += v0.w;
            a1.x += v1.x; a1.y += v1.y; a1.z += v1.z; a1.w += v1.w;
            a2.x += v2.x; a2.y += v2.y; a2.z += v2.z; a2.w += v2.w;
            a3.x += v3.x; a3.y += v3.y; a3.z += v3.z; a3.w += v3.w;
        }
        for (; i < m; i++) {
            int s0 = __shfl_sync(0xffffffffu, sid, i);
            float4 v0 = *(const float4*)(xcol + (size_t)s0 * DD);
            a0.x += v0.x; a0.y += v0.y; a0.z += v0.z; a0.w += v0.w;
        }
    }
    float deg = (float)(e - s);
    float inv = (deg > 0.f) ? 1.0f / deg : 0.f;
    float4 r;
    r.x = (a0.x + a1.x + a2.x + a3.x) * inv;
    r.y = (a0.y + a1.y + a2.y + a3.y) * inv;
    r.z = (a0.z + a1.z + a2.z + a3.z) * inv;
    r.w = (a0.w + a1.w + a2.w + a3.w) * inv;
    *(float4*)(g_agg + (size_t)gw * DD + lane * 4) = r;
}

// fused: out = x + b_l + agg @ W_l^T + x @ W_r^T
// tile 64 rows x 128 cols, 256 threads, micro-tile 4x8, KT=16
__global__ __launch_bounds__(256) void k_gemm(
    const float* __restrict__ x,  const float* __restrict__ Wl,
    const float* __restrict__ bl, const float* __restrict__ Wr,
    float* __restrict__ out, int N)
{
    __shared__ float sAg[16][64];
    __shared__ float sAx[16][64];
    __shared__ float sBl[16][128];
    __shared__ float sBr[16][128];

    int tid = threadIdx.x;
    int tx = tid & 15;        // 0..15 -> 8 output cols
    int ty = tid >> 4;        // 0..15 -> 4 output rows
    int row0 = blockIdx.x * 64;

    float acc[4][8];
#pragma unroll
    for (int i = 0; i < 4; i++)
#pragma unroll
        for (int j = 0; j < 8; j++) acc[i][j] = 0.f;

    int am = tid >> 2;            // 0..63
    int ak = (tid & 3) * 4;       // 0,4,8,12

    for (int kt = 0; kt < 128; kt += 16) {
        // ---- load A tiles (agg and x), guarded on row ----
        int gr = row0 + am;
        float4 va = {0,0,0,0}, vx = {0,0,0,0};
        if (gr < N) {
            va = *(const float4*)(g_agg + (size_t)gr * 128 + kt + ak);
            vx = *(const float4*)(x     + (size_t)gr * 128 + kt + ak);
        }
        sAg[ak + 0][am] = va.x; sAg[ak + 1][am] = va.y;
        sAg[ak + 2][am] = va.z; sAg[ak + 3][am] = va.w;
        sAx[ak + 0][am] = vx.x; sAx[ak + 1][am] = vx.y;
        sAx[ak + 2][am] = vx.z; sAx[ak + 3][am] = vx.w;
        // ---- load B tiles (W_l, W_r rows, transposed into [k][j]) ----
#pragma unroll
        for (int h = 0; h < 2; h++) {
            int l = tid + h * 256;
            int j = l >> 2;
            int kk = (l & 3) * 4;
            float4 vl = *(const float4*)(Wl + (size_t)j * 128 + kt + kk);
            float4 vr = *(const float4*)(Wr + (size_t)j * 128 + kt + kk);
            sBl[kk + 0][j] = vl.x; sBl[kk + 1][j] = vl.y;
            sBl[kk + 2][j] = vl.z; sBl[kk + 3][j] = vl.w;
            sBr[kk + 0][j] = vr.x; sBr[kk + 1][j] = vr.y;
            sBr[kk + 2][j] = vr.z; sBr[kk + 3][j] = vr.w;
        }
        __syncthreads();
#pragma unroll
        for (int kk = 0; kk < 16; kk++) {
            float4 ag = *(const float4*)&sAg[kk][ty * 4];
            float4 xx = *(const float4*)&sAx[kk][ty * 4];
            float4 bl0 = *(const float4*)&sBl[kk][tx * 8];
            float4 bl1 = *(const float4*)&sBl[kk][tx * 8 + 4];
            float4 br0 = *(const float4*)&sBr[kk][tx * 8];
            float4 br1 = *(const float4*)&sBr[kk][tx * 8 + 4];
            float agv[4] = {ag.x, ag.y, ag.z, ag.w};
            float xxv[4] = {xx.x, xx.y, xx.z, xx.w};
            float blv[8] = {bl0.x, bl0.y, bl0.z, bl0.w, bl1.x, bl1.y, bl1.z, bl1.w};
            float brv[8] = {br0.x, br0.y, br0.z, br0.w, br1.x, br1.y, br1.z, br1.w};
#pragma unroll
            for (int i = 0; i < 4; i++)
#pragma unroll
                for (int j = 0; j < 8; j++)
                    acc[i][j] += agv[i] * blv[j] + xxv[i] * brv[j];
        }
        __syncthreads();
    }

    // epilogue: out = x + b_l + acc
    int c0 = tx * 8;
    float4 b0 = *(const float4*)(bl + c0);
    float4 b1 = *(const float4*)(bl + c0 + 4);
#pragma unroll
    for (int i = 0; i < 4; i++) {
        int r = row0 + ty * 4 + i;
        if (r < N) {
            float4 x0 = *(const float4*)(x + (size_t)r * 128 + c0);
            float4 x1 = *(const float4*)(x + (size_t)r * 128 + c0 + 4);
            float4 o0, o1;
            o0.x = x0.x + b0.x + acc[i][0];
            o0.y = x0.y + b0.y + acc[i][1];
            o0.z = x0.z + b0.z + acc[i][2];
            o0.w = x0.w + b0.w + acc[i][3];
            o1.x = x1.x + b1.x + acc[i][4];
            o1.y = x1.y + b1.y + acc[i][5];
            o1.z = x1.z + b1.z + acc[i][6];
            o1.w = x1.w + b1.w + acc[i][7];
            *(float4*)(out + (size_t)r * 128 + c0)     = o0;
            *(float4*)(out + (size_t)r * 128 + c0 + 4) = o1;
        }
    }
}

extern "C" void kernel_launch(void* const* d_in, const int* in_sizes, int n_in,
                              void* d_out, int out_size) {
    const float* x  = (const float*)d_in[0];
    const void*  ei = d_in[1];
    const float* Wl = (const float*)d_in[2];
    const float* bl = (const float*)d_in[3];
    const float* Wr = (const float*)d_in[4];
    float* out = (float*)d_out;

    int N = in_sizes[0] / DD;        // 10000
    int E = in_sizes[1] / 2;         // 640000

    k_detect<<<1, 32>>>((const int*)ei);
    k_zero<<<(NN + 255) / 256, 256>>>();
    k_hist<<<(E + 255) / 256, 256>>>(ei, E);
    k_scan<<<1, 1024>>>();
    k_scatter<<<(E + 255) / 256, 256>>>(ei, E);
    k_agg<<<(NN * 32 + 255) / 256, 256>>>(x);
    k_gemm<<<(N + 63) / 64, 256>>>(x, Wl, bl, Wr, out, N);
}

// round 2
// speedup vs baseline: 1.3161x; 1.3161x over previous
#include <cuda_runtime.h>
#include <cuda_fp16.h>

#define NN 10000
#define DD 128
#define EE 640000
#define GROWS 68

// ---------------- device scratch (no allocations allowed) ----------------
__device__ int    g_deg[NN];
__device__ int    g_rowptr[NN + 1];
__device__ int    g_cursor[NN];
__device__ int    g_srcs[EE];
__device__ float  g_agg[NN * DD];
__device__ __half g_xh[NN * DD];
__device__ int    g_is64;

// packed f32x2 helpers (FFMA2 — only reachable via PTX fma.rn.f32x2)
__device__ __forceinline__ unsigned long long pk2(float a, float b) {
    unsigned long long r;
    asm("mov.b64 %0,{%1,%2};" : "=l"(r) : "f"(a), "f"(b));
    return r;
}
#define FMA2(d, a, b, c) asm("fma.rn.f32x2 %0, %1, %2, %3;" : "=l"(d) : "l"(a), "l"(b), "l"(c))

// ---------------- prep: detect dtype + zero degree + fp16 copy of x ------
__global__ void k_prep(const float* __restrict__ x, const int* __restrict__ ei) {
    int i = blockIdx.x * 256 + threadIdx.x;
    if (i < NN * DD / 4) {
        float4 v = *(const float4*)(x + (size_t)i * 4);
        __half2 h0 = __floats2half2_rn(v.x, v.y);
        __half2 h1 = __floats2half2_rn(v.z, v.w);
        uint2 o;
        o.x = *(unsigned*)&h0;
        o.y = *(unsigned*)&h1;
        *(uint2*)(g_xh + (size_t)i * 4) = o;
    }
    if (i < NN) g_deg[i] = 0;
    if (i == 0) {
        // int64 edge values < 10000 => every odd int32 word is 0 (LE)
        int orv = 0;
#pragma unroll 8
        for (int j = 0; j < 256; j++) orv |= ei[2 * j + 1];
        g_is64 = (orv == 0);
    }
}

__device__ __forceinline__ int load_idx(const void* ei, long long pos) {
    if (g_is64) return (int)((const long long*)ei)[pos];
    return ((const int*)ei)[pos];
}

__global__ void k_hist(const void* __restrict__ ei, int E) {
    int e = blockIdx.x * 256 + threadIdx.x;
    if (e < E) {
        int dst = load_idx(ei, (long long)E + e);
        atomicAdd(&g_deg[dst], 1);
    }
}

// single-block exclusive scan, shfl-based (2 barriers total)
__global__ void k_scan() {
    __shared__ int warpsum[32];
    int t = threadIdx.x;
    int lane = t & 31, wid = t >> 5;
    int base = t * 10;
    int v[10];
    int sum = 0;
#pragma unroll
    for (int i = 0; i < 10; i++) {
        int idx = base + i;
        v[i] = (idx < NN) ? g_deg[idx] : 0;
        sum += v[i];
    }
    int inc = sum;  // inclusive warp scan of thread sums
#pragma unroll
    for (int o = 1; o < 32; o <<= 1) {
        int u = __shfl_up_sync(0xffffffffu, inc, o);
        if (lane >= o) inc += u;
    }
    if (lane == 31) warpsum[wid] = inc;
    __syncthreads();
    if (wid == 0) {
        int w = warpsum[lane];
        int iw = w;
#pragma unroll
        for (int o = 1; o < 32; o <<= 1) {
            int u = __shfl_up_sync(0xffffffffu, iw, o);
            if (lane >= o) iw += u;
        }
        warpsum[lane] = iw - w;  // exclusive warp prefix
    }
    __syncthreads();
    int run = warpsum[wid] + inc - sum;  // block-exclusive prefix for this chunk
#pragma unroll
    for (int i = 0; i < 10; i++) {
        int idx = base + i;
        if (idx < NN) {
            g_rowptr[idx] = run;
            g_cursor[idx] = run;
            run += v[i];
        }
    }
    if (t == 1023) g_rowptr[NN] = run;  // total edges
}

__global__ void k_scatter(const void* __restrict__ ei, int E) {
    int e = blockIdx.x * 256 + threadIdx.x;
    if (e < E) {
        int dst = load_idx(ei, (long long)E + e);
        int src = load_idx(ei, e);
        int pos = atomicAdd(&g_cursor[dst], 1);
        g_srcs[pos] = src;
    }
}

// one warp per node; lane owns 4 cols; fp16 gather (halved L2 traffic),
// fp32 accumulation; 4-deep MLP
__global__ void k_agg() {
    int gw = (blockIdx.x * blockDim.x + threadIdx.x) >> 5;
    int lane = threadIdx.x & 31;
    if (gw >= NN) return;
    int s = g_rowptr[gw], e = g_rowptr[gw + 1];
    float4 a0 = {0, 0, 0, 0}, a1 = {0, 0, 0, 0}, a2 = {0, 0, 0, 0}, a3 = {0, 0, 0, 0};
    const __half* xcol = g_xh + lane * 4;

#define ACC(A, SRC)                                                          \
    {                                                                        \
        uint2 u = *(const uint2*)(xcol + (size_t)(SRC)*DD);                  \
        __half2 h0 = *(__half2*)&u.x, h1 = *(__half2*)&u.y;                  \
        float2 f0 = __half22float2(h0), f1 = __half22float2(h1);             \
        A.x += f0.x; A.y += f0.y; A.z += f1.x; A.w += f1.y;                  \
    }

    for (int base = s; base < e; base += 32) {
        int m = e - base;
        if (m > 32) m = 32;
        int sid = 0;
        if (lane < m) sid = g_srcs[base + lane];
        int i = 0;
        for (; i + 4 <= m; i += 4) {
            int s0 = __shfl_sync(0xffffffffu, sid, i);
            int s1 = __shfl_sync(0xffffffffu, sid, i + 1);
            int s2 = __shfl_sync(0xffffffffu, sid, i + 2);
            int s3 = __shfl_sync(0xffffffffu, sid, i + 3);
            ACC(a0, s0) ACC(a1, s1) ACC(a2, s2) ACC(a3, s3)
        }
        for (; i < m; i++) {
            int s0 = __shfl_sync(0xffffffffu, sid, i);
            ACC(a0, s0)
        }
    }
#undef ACC
    float deg = (float)(e - s);
    float inv = (deg > 0.f) ? 1.0f / deg : 0.f;
    float4 r;
    r.x = (a0.x + a1.x + a2.x + a3.x) * inv;
    r.y = (a0.y + a1.y + a2.y + a3.y) * inv;
    r.z = (a0.z + a1.z + a2.z + a3.z) * inv;
    r.w = (a0.w + a1.w + a2.w + a3.w) * inv;
    *(float4*)(g_agg + (size_t)gw * DD + lane * 4) = r;
}

// fused: out = x + b_l + agg @ W_l^T + x @ W_r^T
// 148 blocks x 68 rows (exactly one wave), 256 threads (warp = row group),
// FFMA2 packed along K: register halves hold even/odd-k partial sums.
__global__ __launch_bounds__(256) void k_gemm(
    const float* __restrict__ x, const float* __restrict__ Wl,
    const float* __restrict__ bl, const float* __restrict__ Wr,
    float* __restrict__ out, int N)
{
    __shared__ float sAg[GROWS][16];
    __shared__ float sAx[GROWS][16];
    __shared__ unsigned long long sBl[8][128];  // [k-pair][col], pre-packed f32x2
    __shared__ unsigned long long sBr[8][128];

    int tid = threadIdx.x;
    int tx = tid & 31;   // col group: cols {tx, tx+32, tx+64, tx+96}
    int ty = tid >> 5;   // row group: rows {ty + 8*i}
    int row0 = blockIdx.x * GROWS;

    unsigned long long acc2[9][4];
#pragma unroll
    for (int i = 0; i < 9; i++)
#pragma unroll
        for (int j = 0; j < 4; j++) acc2[i][j] = 0ULL;

    for (int kt = 0; kt < 128; kt += 16) {
        // A tiles: [row][k] layout, float4 stores (conflict-free)
        for (int l = tid; l < GROWS * 4; l += 256) {
            int am = l >> 2, ak = (l & 3) * 4;
            int gr = row0 + am;
            float4 va = {0, 0, 0, 0}, vx = {0, 0, 0, 0};
            if (gr < N) {
                va = *(const float4*)(g_agg + (size_t)gr * 128 + kt + ak);
                vx = *(const float4*)(x + (size_t)gr * 128 + kt + ak);
            }
            *(float4*)&sAg[am][ak] = va;
            *(float4*)&sAx[am][ak] = vx;
        }
        // B tiles: pack consecutive-k pairs into f32x2
#pragma unroll
        for (int h = 0; h < 2; h++) {
            int l = tid + h * 256;
            int j = l >> 2;
            int kk = (l & 3) * 4;
            int kp0 = (l & 3) * 2;
            float4 vl = *(const float4*)(Wl + (size_t)j * 128 + kt + kk);
            float4 vr = *(const float4*)(Wr + (size_t)j * 128 + kt + kk);
            sBl[kp0][j] = pk2(vl.x, vl.y);
            sBl[kp0 + 1][j] = pk2(vl.z, vl.w);
            sBr[kp0][j] = pk2(vr.x, vr.y);
            sBr[kp0 + 1][j] = pk2(vr.z, vr.w);
        }
        __syncthreads();
#pragma unroll
        for (int kp = 0; kp < 8; kp++) {
            unsigned long long blv[4], brv[4];
#pragma unroll
            for (int jj = 0; jj < 4; jj++) {
                blv[jj] = sBl[kp][tx + 32 * jj];
                brv[jj] = sBr[kp][tx + 32 * jj];
            }
#pragma unroll
            for (int i = 0; i < 9; i++) {
                if (i < 8 || ty < 4) {  // row ty+64 exists only for ty<4 (68 rows)
                    int rl = ty + 8 * i;
                    unsigned long long ag = *(const unsigned long long*)&sAg[rl][2 * kp];
                    unsigned long long ax = *(const unsigned long long*)&sAx[rl][2 * kp];
#pragma unroll
                    for (int jj = 0; jj < 4; jj++) {
                        FMA2(acc2[i][jj], ag, blv[jj], acc2[i][jj]);
                        FMA2(acc2[i][jj], ax, brv[jj], acc2[i][jj]);
                    }
                }
            }
        }
        __syncthreads();
    }

    // epilogue: fold even/odd halves, add x + b_l
#pragma unroll
    for (int i = 0; i < 9; i++) {
        int rl = ty + 8 * i;
        int r = row0 + rl;
        if ((i < 8 || ty < 4) && r < N) {
#pragma unroll
            for (int jj = 0; jj < 4; jj++) {
                int c = tx + 32 * jj;
                float2 f = *(float2*)&acc2[i][jj];
                out[(size_t)r * 128 + c] = x[(size_t)r * 128 + c] + bl[c] + f.x + f.y;
            }
        }
    }
}

extern "C" void kernel_launch(void* const* d_in, const int* in_sizes, int n_in,
                              void* d_out, int out_size) {
    const float* x = (const float*)d_in[0];
    const void* ei = d_in[1];
    const float* Wl = (const float*)d_in[2];
    const float* bl = (const float*)d_in[3];
    const float* Wr = (const float*)d_in[4];
    float* out = (float*)d_out;

    int N = in_sizes[0] / DD;  // 10000
    int E = in_sizes[1] / 2;   // 640000

    k_prep<<<(NN * DD / 4 + 255) / 256, 256>>>(x, (const int*)ei);
    k_hist<<<(E + 255) / 256, 256>>>(ei, E);
    k_scan<<<1, 1024>>>();
    k_scatter<<<(E + 255) / 256, 256>>>(ei, E);
    k_agg<<<(NN * 32 + 255) / 256, 256>>>();
    k_gemm<<<(N + GROWS - 1) / GROWS, 256>>>(x, Wl, bl, Wr, out, N);
}